// round 1
// baseline (speedup 1.0000x reference)
#include <cuda_runtime.h>
#include <math.h>

// Problem constants
#define KBINS 256
#define Q 8
#define KQ (KBINS * Q)          // 2048 sub-bins
#define BATCH 8
#define NPB (512 * 512)          // 262144 elements per batch
#define CTAS_PER_BATCH 64
#define ELEMS_PER_CTA (NPB / CTAS_PER_BATCH)   // 4096
#define P1_THREADS 256
#define P1_ITERS (ELEMS_PER_CTA / 4 / P1_THREADS) // 4 float4 iters per thread
#define SCALE 2048.0f            // count-encoding scale
#define WLEN 128                 // convolution window taps (jj in [-60, 67])
#define JJ_LO (-60)

// Per-CTA partial histograms (combined cnt/rsum encoding). 512*2048*4B = 4MB.
__device__ float g_part[BATCH * CTAS_PER_BATCH * KQ];

// ---------------------------------------------------------------------------
// Pass 1: quantize each x into one of 2048 sub-bins; accumulate a single
// float per element encoding (count, residual): val = SCALE + r, r in [-.5,.5]
// sub-bin units. One shared atomicAdd per element (spread addresses).
// ---------------------------------------------------------------------------
__global__ void __launch_bounds__(P1_THREADS, 8)
hist_pass1(const float* __restrict__ x) {
    __shared__ float sh[KQ];
    const int tid = threadIdx.x;

    #pragma unroll
    for (int i = tid; i < KQ; i += P1_THREADS) sh[i] = 0.0f;
    __syncthreads();

    const int b = blockIdx.x / CTAS_PER_BATCH;
    const int c = blockIdx.x % CTAS_PER_BATCH;
    const float4* __restrict__ xp =
        reinterpret_cast<const float4*>(x + (size_t)b * NPB + (size_t)c * ELEMS_PER_CTA);

    #pragma unroll
    for (int it = 0; it < P1_ITERS; it++) {
        float4 v = xp[it * P1_THREADS + tid];
        float vals[4] = {v.x, v.y, v.z, v.w};
        #pragma unroll
        for (int j = 0; j < 4; j++) {
            float u = vals[j] * (float)KQ;        // position in sub-bin units
            int idx = (int)u;
            idx = max(0, min(KQ - 1, idx));
            float r = u - (float)idx - 0.5f;      // residual within sub-bin
            atomicAdd(&sh[idx], SCALE + r);
        }
    }
    __syncthreads();

    float* __restrict__ dst = g_part + (size_t)blockIdx.x * KQ;
    #pragma unroll
    for (int i = tid; i < KQ; i += P1_THREADS) dst[i] = sh[i];
}

// ---------------------------------------------------------------------------
// Pass 2: one CTA per batch. Reduce 64 partials, decode (cnt, rsum), then
// each thread k convolves a 128-tap window of precomputed kernel weights:
//   p[k] = (1/N) * sum_m [ cnt_m * g(d_m) + rsum_m * Delta * g'(d_m) ]
// Shared arrays padded (stride 33 per 32) to avoid 8-way bank conflicts
// from the stride-8 access pattern.
// ---------------------------------------------------------------------------
#define PADI(m) ((m) + ((m) >> 5))
#define KQ_PAD (KQ + (KQ >> 5))

__global__ void __launch_bounds__(256, 1)
hist_pass2(float* __restrict__ out) {
    __shared__ float s_cnt[KQ_PAD];
    __shared__ float s_rs[KQ_PAD];
    __shared__ float s_w0[WLEN];
    __shared__ float s_w1[WLEN];

    const int b = blockIdx.x;
    const int tid = threadIdx.x;   // 256 threads, one per output bin k

    // Reduce partials across the 64 CTAs of this batch, then decode.
    for (int m = tid; m < KQ; m += 256) {
        const float* __restrict__ src = g_part + (size_t)b * CTAS_PER_BATCH * KQ + m;
        float s = 0.0f;
        #pragma unroll
        for (int c = 0; c < CTAS_PER_BATCH; c++) s += src[(size_t)c * KQ];
        float cnt = rintf(s * (1.0f / SCALE));
        float rs  = s - cnt * SCALE;
        s_cnt[PADI(m)] = cnt;
        s_rs[PADI(m)]  = rs;
    }

    // Precompute window weights in double (128 taps; cost is nil).
    // d = Delta*(jj - 3.5) where Delta = 1/KQ; args a+- = (jj - 3.5 +- 4)/3.2
    // w0 = sigmoid(a+) - sigmoid(a-)
    // w1 = Delta*g'(d) = [sig'(a+) - sig'(a-)]/3.2
    if (tid < WLEN) {
        double jj = (double)(tid + JJ_LO);
        double ap = (jj - 3.5 + 4.0) / 3.2;
        double am = (jj - 3.5 - 4.0) / 3.2;
        double sp = 1.0 / (1.0 + exp(-ap));
        double sm = 1.0 / (1.0 + exp(-am));
        s_w0[tid] = (float)(sp - sm);
        s_w1[tid] = (float)((sp * (1.0 - sp) - sm * (1.0 - sm)) / 3.2);
    }
    __syncthreads();

    // 128-tap convolution per output bin.
    const int base = tid * Q + JJ_LO;
    float acc = 0.0f;
    #pragma unroll 8
    for (int w = 0; w < WLEN; w++) {
        int m = base + w;
        if (m >= 0 && m < KQ) {
            int mp = PADI(m);
            acc = fmaf(s_cnt[mp], s_w0[w], acc);
            acc = fmaf(s_rs[mp],  s_w1[w], acc);
        }
    }
    out[b * KBINS + tid] = acc * (1.0f / (float)NPB);
}

extern "C" void kernel_launch(void* const* d_in, const int* in_sizes, int n_in,
                              void* d_out, int out_size) {
    (void)in_sizes; (void)n_in; (void)out_size;
    const float* x = (const float*)d_in[0];
    float* out = (float*)d_out;

    hist_pass1<<<BATCH * CTAS_PER_BATCH, P1_THREADS>>>(x);
    hist_pass2<<<BATCH, 256>>>(out);
}

// round 2
// speedup vs baseline: 1.2092x; 1.2092x over previous
#include <cuda_runtime.h>
#include <math.h>

// Problem constants
#define KBINS 256
#define Q 8
#define KQ (KBINS * Q)          // 2048 sub-bins
#define BATCH 8
#define NPB (512 * 512)          // 262144 elements per batch
#define CTAS_PER_BATCH 64
#define ELEMS_PER_CTA (NPB / CTAS_PER_BATCH)   // 4096
#define P1_THREADS 256
#define P1_ITERS (ELEMS_PER_CTA / 4 / P1_THREADS) // 4 float4 iters per thread
#define SCALE 2048.0f            // count-encoding scale
#define WLEN 128                 // convolution window taps (jj in [-60, 67])
#define JJ_LO (-60)

// One combined (cnt,rsum) histogram per batch: 8 * 2048 * 4B = 64 KB.
__device__ float g_hist[BATCH * KQ];

// ---------------------------------------------------------------------------
// Pass 1: quantize each x into one of 2048 sub-bins; accumulate a single
// float per element encoding (count, residual): val = SCALE + r, r in [-.5,.5]
// sub-bin units. One shared atomicAdd per element, then flush the per-CTA
// shared histogram straight into the per-batch global histogram via REDG
// (no 4MB partials materialized -> pass 2 reads only 64KB).
// ---------------------------------------------------------------------------
__global__ void __launch_bounds__(P1_THREADS, 8)
hist_pass1(const float* __restrict__ x) {
    __shared__ float sh[KQ];
    const int tid = threadIdx.x;

    #pragma unroll
    for (int i = tid; i < KQ; i += P1_THREADS) sh[i] = 0.0f;
    __syncthreads();

    const int b = blockIdx.x / CTAS_PER_BATCH;
    const int c = blockIdx.x % CTAS_PER_BATCH;
    const float4* __restrict__ xp =
        reinterpret_cast<const float4*>(x + (size_t)b * NPB + (size_t)c * ELEMS_PER_CTA);

    #pragma unroll
    for (int it = 0; it < P1_ITERS; it++) {
        float4 v = xp[it * P1_THREADS + tid];
        float vals[4] = {v.x, v.y, v.z, v.w};
        #pragma unroll
        for (int j = 0; j < 4; j++) {
            float u = vals[j] * (float)KQ;        // position in sub-bin units
            int idx = (int)u;
            idx = max(0, min(KQ - 1, idx));
            float r = u - (float)idx - 0.5f;      // residual within sub-bin
            atomicAdd(&sh[idx], SCALE + r);
        }
    }
    __syncthreads();

    float* __restrict__ dst = g_hist + (size_t)b * KQ;
    #pragma unroll
    for (int i = tid; i < KQ; i += P1_THREADS) {
        float v = sh[i];
        if (v != 0.0f) atomicAdd(&dst[i], v);     // REDG, spread addresses
    }
}

// ---------------------------------------------------------------------------
// Pass 2: one CTA per batch. Read the 2048-entry per-batch histogram (8KB),
// decode (cnt, rsum), then each thread k convolves a 128-tap window:
//   p[k] = (1/N) * sum_m [ cnt_m * g(d_m) + rsum_m * Delta * g'(d_m) ]
// Shared arrays padded (stride 33 per 32) to avoid 8-way bank conflicts
// from the stride-8 access pattern.
// ---------------------------------------------------------------------------
#define PADI(m) ((m) + ((m) >> 5))
#define KQ_PAD (KQ + (KQ >> 5))

__global__ void __launch_bounds__(256, 1)
hist_pass2(float* __restrict__ out) {
    __shared__ float s_cnt[KQ_PAD];
    __shared__ float s_rs[KQ_PAD];
    __shared__ float s_w0[WLEN];
    __shared__ float s_w1[WLEN];

    const int b = blockIdx.x;
    const int tid = threadIdx.x;   // 256 threads, one per output bin k

    // Load + decode the per-batch histogram.
    const float* __restrict__ src = g_hist + (size_t)b * KQ;
    #pragma unroll
    for (int m = tid; m < KQ; m += 256) {
        float s = src[m];
        float cnt = rintf(s * (1.0f / SCALE));
        float rs  = s - cnt * SCALE;
        s_cnt[PADI(m)] = cnt;
        s_rs[PADI(m)]  = rs;
    }

    // Precompute window weights in double (128 taps; cost is nil).
    // d = Delta*(jj - 3.5) where Delta = 1/KQ; args a+- = (jj - 3.5 +- 4)/3.2
    // w0 = sigmoid(a+) - sigmoid(a-)
    // w1 = Delta*g'(d) = [sig'(a+) - sig'(a-)]/3.2
    if (tid < WLEN) {
        double jj = (double)(tid + JJ_LO);
        double ap = (jj - 3.5 + 4.0) / 3.2;
        double am = (jj - 3.5 - 4.0) / 3.2;
        double sp = 1.0 / (1.0 + exp(-ap));
        double sm = 1.0 / (1.0 + exp(-am));
        s_w0[tid] = (float)(sp - sm);
        s_w1[tid] = (float)((sp * (1.0 - sp) - sm * (1.0 - sm)) / 3.2);
    }
    __syncthreads();

    // 128-tap convolution per output bin.
    const int base = tid * Q + JJ_LO;
    float acc = 0.0f;
    #pragma unroll 8
    for (int w = 0; w < WLEN; w++) {
        int m = base + w;
        if (m >= 0 && m < KQ) {
            int mp = PADI(m);
            acc = fmaf(s_cnt[mp], s_w0[w], acc);
            acc = fmaf(s_rs[mp],  s_w1[w], acc);
        }
    }
    out[b * KBINS + tid] = acc * (1.0f / (float)NPB);
}

extern "C" void kernel_launch(void* const* d_in, const int* in_sizes, int n_in,
                              void* d_out, int out_size) {
    (void)in_sizes; (void)n_in; (void)out_size;
    const float* x = (const float*)d_in[0];
    float* out = (float*)d_out;

    void* hist_ptr = nullptr;
    cudaGetSymbolAddress(&hist_ptr, g_hist);
    cudaMemsetAsync(hist_ptr, 0, BATCH * KQ * sizeof(float));

    hist_pass1<<<BATCH * CTAS_PER_BATCH, P1_THREADS>>>(x);
    hist_pass2<<<BATCH, 256>>>(out);
}

// round 3
// speedup vs baseline: 1.2336x; 1.0202x over previous
#include <cuda_runtime.h>
#include <math.h>

// Problem constants
#define KBINS 256
#define Q 8
#define KQ (KBINS * Q)          // 2048 sub-bins
#define BATCH 8
#define NPB (512 * 512)          // 262144 elements per batch
#define CTAS_PER_BATCH 64
#define ELEMS_PER_CTA (NPB / CTAS_PER_BATCH)   // 4096
#define P1_THREADS 256
#define P1_ITERS (ELEMS_PER_CTA / 4 / P1_THREADS) // 4 float4 iters per thread
#define SCALE 2048.0f            // count-encoding scale
#define WLEN 128                 // convolution window taps (jj in [-60, 67])
#define JJ_LO (-60)

#define PADI(m) ((m) + ((m) >> 5))
#define KQ_PAD (KQ + (KQ >> 5))  // 2112

// One combined (cnt,rsum) histogram per batch: 8 * 2048 * 4B = 64 KB.
// Zero-initialized at module load; the finishing CTA re-zeroes it each launch
// so the kernel is graph-replay deterministic.
__device__ float g_hist[BATCH * KQ];
__device__ unsigned int g_sync[BATCH];

// ---------------------------------------------------------------------------
// Fused kernel.
// Phase A (all 512 CTAs): quantize each x into one of 2048 sub-bins;
//   one shared atomicAdd per element encoding (count, residual):
//   val = SCALE + r, r in [-0.5, 0.5] sub-bin units. Flush shared histogram
//   into the per-batch global histogram via REDG (spread addresses).
// Phase B (last CTA per batch): read the 8KB batch histogram from L2
//   (__ldcg), decode (cnt, rsum), 128-tap convolution with float-precision
//   weights, write 256 outputs, reset histogram + counter for next replay.
// ---------------------------------------------------------------------------
__global__ void __launch_bounds__(P1_THREADS, 8)
hist_fused(const float* __restrict__ x, float* __restrict__ out) {
    // Overlaid shared memory: phase A uses the first KQ floats as the local
    // histogram; phase B reuses the pool as padded cnt/rs arrays + weights.
    __shared__ float pool[KQ_PAD * 2 + 2 * WLEN];   // ~17.9 KB
    __shared__ bool is_last;
    float* sh = pool;

    const int tid = threadIdx.x;
    const int b = blockIdx.x / CTAS_PER_BATCH;
    const int c = blockIdx.x % CTAS_PER_BATCH;

    #pragma unroll
    for (int i = tid; i < KQ; i += P1_THREADS) sh[i] = 0.0f;
    __syncthreads();

    // --- Phase A: local accumulation ---
    const float4* __restrict__ xp =
        reinterpret_cast<const float4*>(x + (size_t)b * NPB + (size_t)c * ELEMS_PER_CTA);

    #pragma unroll
    for (int it = 0; it < P1_ITERS; it++) {
        float4 v = xp[it * P1_THREADS + tid];
        float vals[4] = {v.x, v.y, v.z, v.w};
        #pragma unroll
        for (int j = 0; j < 4; j++) {
            float u = vals[j] * (float)KQ;        // position in sub-bin units
            int idx = (int)u;
            idx = max(0, min(KQ - 1, idx));
            float r = u - (float)idx - 0.5f;      // residual within sub-bin
            atomicAdd(&sh[idx], SCALE + r);
        }
    }
    __syncthreads();

    // Flush to the per-batch global histogram (REDG, spread addresses).
    float* __restrict__ gh = g_hist + (size_t)b * KQ;
    #pragma unroll
    for (int i = tid; i < KQ; i += P1_THREADS) {
        float v = sh[i];
        if (v != 0.0f) atomicAdd(&gh[i], v);
    }

    // --- Arrival protocol: last CTA of this batch proceeds to phase B ---
    __threadfence();
    if (tid == 0) {
        unsigned int old = atomicAdd(&g_sync[b], 1u);
        is_last = (old == CTAS_PER_BATCH - 1);
    }
    __syncthreads();
    if (!is_last) return;

    // --- Phase B: decode + convolution (one CTA per batch) ---
    float* s_cnt = pool;                    // [KQ_PAD]
    float* s_rs  = pool + KQ_PAD;           // [KQ_PAD]
    float* s_w0  = pool + 2 * KQ_PAD;       // [WLEN]
    float* s_w1  = s_w0 + WLEN;             // [WLEN]

    #pragma unroll
    for (int m = tid; m < KQ; m += P1_THREADS) {
        float s = __ldcg(&gh[m]);           // L2-coherent read (skip L1)
        float cnt = rintf(s * (1.0f / SCALE));
        float rs  = s - cnt * SCALE;
        s_cnt[PADI(m)] = cnt;
        s_rs[PADI(m)]  = rs;
        gh[m] = 0.0f;                       // reset for the next graph replay
    }
    if (tid == 0) g_sync[b] = 0u;

    // Window weights in float. d = Delta*(jj - 3.5), args (jj - 3.5 +- 4)/3.2
    //   w0 = sigmoid(a+) - sigmoid(a-)
    //   w1 = Delta*g'(d) = [sig'(a+) - sig'(a-)]/3.2
    if (tid < WLEN) {
        float jj = (float)(tid + JJ_LO);
        float ap = (jj - 3.5f + 4.0f) * (1.0f / 3.2f);
        float am = (jj - 3.5f - 4.0f) * (1.0f / 3.2f);
        float sp = 1.0f / (1.0f + expf(-ap));
        float sm = 1.0f / (1.0f + expf(-am));
        s_w0[tid] = sp - sm;
        s_w1[tid] = (sp * (1.0f - sp) - sm * (1.0f - sm)) * (1.0f / 3.2f);
    }
    __syncthreads();

    // 128-tap convolution per output bin (thread tid = bin k).
    const int base = tid * Q + JJ_LO;
    float acc = 0.0f;
    #pragma unroll 8
    for (int w = 0; w < WLEN; w++) {
        int m = base + w;
        if (m >= 0 && m < KQ) {
            int mp = PADI(m);
            acc = fmaf(s_cnt[mp], s_w0[w], acc);
            acc = fmaf(s_rs[mp],  s_w1[w], acc);
        }
    }
    out[b * KBINS + tid] = acc * (1.0f / (float)NPB);
}

extern "C" void kernel_launch(void* const* d_in, const int* in_sizes, int n_in,
                              void* d_out, int out_size) {
    (void)in_sizes; (void)n_in; (void)out_size;
    const float* x = (const float*)d_in[0];
    float* out = (float*)d_out;
    hist_fused<<<BATCH * CTAS_PER_BATCH, P1_THREADS>>>(x, out);
}

// round 4
// speedup vs baseline: 1.6851x; 1.3660x over previous
#include <cuda_runtime.h>
#include <math.h>

// Problem constants
#define KBINS 256
#define Q 4
#define KQ (KBINS * Q)          // 1024 sub-bins
#define BATCH 8
#define NPB (512 * 512)          // 262144 elements per batch
#define NPB4 (NPB / 4)           // 65536 float4 per batch
#define CTAS_PER_BATCH 74        // 8*74 = 592 = 148*4  -> exactly 4 CTAs/SM
#define P1_THREADS 256
#define SCALE 4096.0f            // count-encoding scale (max batch cnt ~340 << 4096/... )
#define WLEN 32                  // convolution window taps, jj in [-14, 17]
#define JJ_LO (-14)

#define PAD4(m) ((m) + ((m) >> 2))   // stride-4 conflict-free padding (gcd(5,32)=1)
#define KQ_PAD (KQ + (KQ >> 2))      // 1280

// One combined (cnt,rsum) histogram per batch: 8 * 1024 * 4B = 32 KB.
// Zero at module load; the finishing CTA re-zeroes it each launch so the
// kernel is graph-replay deterministic.
__device__ float g_hist[BATCH * KQ];
__device__ unsigned int g_sync[BATCH];

__device__ __forceinline__ void red_add_v4(float* addr, float4 v) {
    asm volatile("red.global.add.v4.f32 [%0], {%1,%2,%3,%4};"
                 :: "l"(addr), "f"(v.x), "f"(v.y), "f"(v.z), "f"(v.w)
                 : "memory");
}

// ---------------------------------------------------------------------------
// Fused kernel.
// Phase A (all 592 CTAs, perfectly balanced): quantize each x into one of
//   1024 sub-bins; one shared atomicAdd per element encoding (count,
//   residual): val = SCALE + r, r in [-0.5, 0.5] sub-bin units. Flush the
//   4KB shared histogram with 256 red.global.add.v4.f32 (1 per thread).
// Phase B (last CTA per batch): read the 4KB batch histogram from L2,
//   decode (cnt, rsum), 32-tap convolution, write 256 outputs, reset state.
// ---------------------------------------------------------------------------
__global__ void __launch_bounds__(P1_THREADS, 8)
hist_fused(const float* __restrict__ x, float* __restrict__ out) {
    __shared__ float pool[2 * KQ_PAD + 2 * WLEN];   // 2624 floats; phase A uses first KQ
    __shared__ bool is_last;
    float* sh = pool;

    const int tid = threadIdx.x;
    const int b = blockIdx.y;
    const int c = blockIdx.x;

    ((float4*)sh)[tid] = make_float4(0.f, 0.f, 0.f, 0.f);
    __syncthreads();

    // --- Phase A: local accumulation over this CTA's balanced range ---
    const float4* __restrict__ xp = reinterpret_cast<const float4*>(x) + (size_t)b * NPB4;
    const int i_lo = (c * NPB4) / CTAS_PER_BATCH;
    const int i_hi = ((c + 1) * NPB4) / CTAS_PER_BATCH;

    for (int i = i_lo + tid; i < i_hi; i += P1_THREADS) {
        float4 v = xp[i];
        float vals[4] = {v.x, v.y, v.z, v.w};
        #pragma unroll
        for (int j = 0; j < 4; j++) {
            float u = vals[j] * (float)KQ;        // position in sub-bin units
            float fidx = floorf(u);
            int idx = (int)fidx;
            idx = max(0, min(KQ - 1, idx));
            // encodes count (SCALE) + residual (u - fidx - 0.5) in one float
            atomicAdd(&sh[idx], u - fidx + (SCALE - 0.5f));
        }
    }
    __syncthreads();

    // Flush: one v4 reduction per thread (1024 bins / 4).
    float* __restrict__ gh = g_hist + (size_t)b * KQ;
    {
        float4 vv = ((const float4*)sh)[tid];
        red_add_v4(&gh[tid * 4], vv);
    }

    // --- Arrival protocol: last CTA of this batch proceeds to phase B ---
    __threadfence();
    if (tid == 0) {
        unsigned int old = atomicAdd(&g_sync[b], 1u);
        is_last = (old == CTAS_PER_BATCH - 1);
    }
    __syncthreads();
    if (!is_last) return;

    // --- Phase B: decode + convolution (one CTA per batch) ---
    float* s_cnt = pool;                    // [KQ_PAD]
    float* s_rs  = pool + KQ_PAD;           // [KQ_PAD]
    float* s_w0  = pool + 2 * KQ_PAD;       // [WLEN]
    float* s_w1  = s_w0 + WLEN;             // [WLEN]

    #pragma unroll
    for (int m = tid; m < KQ; m += P1_THREADS) {
        float s = __ldcg(&gh[m]);           // L2-coherent read
        float cnt = rintf(s * (1.0f / SCALE));
        float rs  = s - cnt * SCALE;
        s_cnt[PAD4(m)] = cnt;
        s_rs[PAD4(m)]  = rs;
        gh[m] = 0.0f;                       // reset for the next graph replay
    }
    if (tid == 0) g_sync[b] = 0u;

    // Window weights (float). With Q=4, Delta = 1/1024:
    //   d = Delta*(jj - 1.5), args a± = 0.625*(jj + 0.5) / 0.625*(jj - 3.5)
    //   w0 = sigmoid(a+) - sigmoid(a-);  w1 = 0.625*[sig'(a+) - sig'(a-)]
    if (tid < WLEN) {
        float jj = (float)(tid + JJ_LO);
        float ap = 0.625f * (jj + 0.5f);
        float am = 0.625f * (jj - 3.5f);
        float sp = 1.0f / (1.0f + __expf(-ap));
        float sm = 1.0f / (1.0f + __expf(-am));
        s_w0[tid] = sp - sm;
        s_w1[tid] = (sp * (1.0f - sp) - sm * (1.0f - sm)) * 0.625f;
    }
    __syncthreads();

    // 32-tap convolution per output bin (thread tid = bin k).
    const int base = tid * Q + JJ_LO;
    float acc = 0.0f;
    #pragma unroll
    for (int w = 0; w < WLEN; w++) {
        int m = base + w;
        if (m >= 0 && m < KQ) {
            int mp = PAD4(m);
            acc = fmaf(s_cnt[mp], s_w0[w], acc);
            acc = fmaf(s_rs[mp],  s_w1[w], acc);
        }
    }
    out[b * KBINS + tid] = acc * (1.0f / (float)NPB);
}

extern "C" void kernel_launch(void* const* d_in, const int* in_sizes, int n_in,
                              void* d_out, int out_size) {
    (void)in_sizes; (void)n_in; (void)out_size;
    const float* x = (const float*)d_in[0];
    float* out = (float*)d_out;
    dim3 grid(CTAS_PER_BATCH, BATCH);
    hist_fused<<<grid, P1_THREADS>>>(x, out);
}